// round 10
// baseline (speedup 1.0000x reference)
#include <cuda_runtime.h>
#include <cstdint>

#define H        256
#define FOURH    1024
#define NG       2048
#define APG      64
#define GRIDA    444          // attention: 3 CTAs per SM
#define TILE_B   (APG*H*4)    // 65536 bytes per graph tile

// ---------------- device scratch ----------------
__device__ float g_Wc[FOURH * H];      // W_ih + W_hh   [1024,256]
__device__ float g_bc[FOURH];          // b_ih + b_hh
__device__ float g_q0[H];              // step-0 q (graph-invariant)
__device__ float g_c0[H];              // step-0 c (graph-invariant)
__device__ float g_c [NG * H];         // per-graph cell state
__device__ float g_h [NG * H];         // h = r of previous step
__device__ float g_gates[NG * FOURH];  // GEMM output (raw, no bias)

__device__ __forceinline__ float sigmoidf_(float v) {
    return 1.0f / (1.0f + __expf(-v));
}

// ---------------- prep ----------------
__global__ void prep_kernel(const float* __restrict__ W_ih,
                            const float* __restrict__ W_hh,
                            const float* __restrict__ b_ih,
                            const float* __restrict__ b_hh) {
    int idx = blockIdx.x * 256 + threadIdx.x;
    if (idx < FOURH * H) g_Wc[idx] = W_ih[idx] + W_hh[idx];
    if (idx < FOURH)     g_bc[idx] = b_ih[idx] + b_hh[idx];
    if (idx < H) {
        float gi = b_ih[idx]       + b_hh[idx];
        float gg = b_ih[512 + idx] + b_hh[512 + idx];
        float go = b_ih[768 + idx] + b_hh[768 + idx];
        float c  = sigmoidf_(gi) * tanhf(gg);
        g_c0[idx] = c;
        g_q0[idx] = sigmoidf_(go) * tanhf(c);
    }
}

// ---------------- packed f32x2 helpers ----------------
__device__ __forceinline__ unsigned long long pack2(float lo, float hi) {
    unsigned long long r;
    asm("mov.b64 %0, {%1, %2};" : "=l"(r) : "f"(lo), "f"(hi));
    return r;
}
__device__ __forceinline__ void ffma2(unsigned long long& d,
                                      unsigned long long a,
                                      unsigned long long b) {
    asm("fma.rn.f32x2 %0, %1, %2, %0;" : "+l"(d) : "l"(a), "l"(b));
}

// ---------------- GEMM: gates = h @ Wc^T (f32x2 FMA) — R2/R3 proven ----------------
__global__ void __launch_bounds__(256) gemm_gates_kernel() {
    __shared__ float As[2][16][128];
    __shared__ float Bs[2][16][64];

    int tid = threadIdx.x;
    int tx  = tid & 15;
    int ty  = tid >> 4;
    int mb  = blockIdx.y * 128;
    int nb  = blockIdx.x * 64;

    int a_r0 = tid >> 2,  a_k = tid & 3;
    int a_r1 = (tid + 256) >> 2;
    int b_r  = tid >> 2,  b_k = tid & 3;

    unsigned long long acc[4][4];
    #pragma unroll
    for (int p = 0; p < 4; ++p)
        #pragma unroll
        for (int j = 0; j < 4; ++j) acc[p][j] = 0ull;

    float4 av0, av1, bv;
    av0 = *(const float4*)&g_h [(size_t)(mb + a_r0) * H + a_k * 4];
    av1 = *(const float4*)&g_h [(size_t)(mb + a_r1) * H + a_k * 4];
    bv  = *(const float4*)&g_Wc[(size_t)(nb + b_r ) * H + b_k * 4];
    {
        As[0][a_k*4+0][a_r0] = av0.x; As[0][a_k*4+1][a_r0] = av0.y;
        As[0][a_k*4+2][a_r0] = av0.z; As[0][a_k*4+3][a_r0] = av0.w;
        As[0][a_k*4+0][a_r1] = av1.x; As[0][a_k*4+1][a_r1] = av1.y;
        As[0][a_k*4+2][a_r1] = av1.z; As[0][a_k*4+3][a_r1] = av1.w;
        Bs[0][b_k*4+0][b_r]  = bv.x;  Bs[0][b_k*4+1][b_r]  = bv.y;
        Bs[0][b_k*4+2][b_r]  = bv.z;  Bs[0][b_k*4+3][b_r]  = bv.w;
    }
    __syncthreads();

    const int NS = H / 16;
    for (int s = 0; s < NS; ++s) {
        int buf = s & 1;
        if (s + 1 < NS) {
            int kk = (s + 1) * 16;
            av0 = *(const float4*)&g_h [(size_t)(mb + a_r0) * H + kk + a_k * 4];
            av1 = *(const float4*)&g_h [(size_t)(mb + a_r1) * H + kk + a_k * 4];
            bv  = *(const float4*)&g_Wc[(size_t)(nb + b_r ) * H + kk + b_k * 4];
        }
        #pragma unroll
        for (int k = 0; k < 16; ++k) {
            unsigned long long a2[4];
            #pragma unroll
            for (int p = 0; p < 4; ++p)
                a2[p] = *(const unsigned long long*)&As[buf][k][ty * 8 + 2 * p];
            float4 b4 = *(const float4*)&Bs[buf][k][tx * 4];
            unsigned long long b2[4];
            b2[0] = pack2(b4.x, b4.x); b2[1] = pack2(b4.y, b4.y);
            b2[2] = pack2(b4.z, b4.z); b2[3] = pack2(b4.w, b4.w);
            #pragma unroll
            for (int p = 0; p < 4; ++p)
                #pragma unroll
                for (int j = 0; j < 4; ++j)
                    ffma2(acc[p][j], a2[p], b2[j]);
        }
        if (s + 1 < NS) {
            int nbuf = 1 - buf;
            As[nbuf][a_k*4+0][a_r0] = av0.x; As[nbuf][a_k*4+1][a_r0] = av0.y;
            As[nbuf][a_k*4+2][a_r0] = av0.z; As[nbuf][a_k*4+3][a_r0] = av0.w;
            As[nbuf][a_k*4+0][a_r1] = av1.x; As[nbuf][a_k*4+1][a_r1] = av1.y;
            As[nbuf][a_k*4+2][a_r1] = av1.z; As[nbuf][a_k*4+3][a_r1] = av1.w;
            Bs[nbuf][b_k*4+0][b_r]  = bv.x;  Bs[nbuf][b_k*4+1][b_r]  = bv.y;
            Bs[nbuf][b_k*4+2][b_r]  = bv.z;  Bs[nbuf][b_k*4+3][b_r]  = bv.w;
        }
        __syncthreads();
    }

    #pragma unroll
    for (int p = 0; p < 4; ++p) {
        float lo[4], hi[4];
        #pragma unroll
        for (int j = 0; j < 4; ++j) {
            union { unsigned long long u; float2 f; } cv;
            cv.u = acc[p][j];
            lo[j] = cv.f.x; hi[j] = cv.f.y;
        }
        int m0 = mb + ty * 8 + 2 * p;
        *(float4*)&g_gates[(size_t)m0       * FOURH + nb + tx * 4] =
            make_float4(lo[0], lo[1], lo[2], lo[3]);
        *(float4*)&g_gates[(size_t)(m0 + 1) * FOURH + nb + tx * 4] =
            make_float4(hi[0], hi[1], hi[2], hi[3]);
    }
}

// ---------------- persistent fused attention (R3 pattern, 3 CTAs/SM) ----------------
// mode 0: q = q0; mode 1: q,c from gates & c0; mode 2: final -> out
#define ATT_FLOATS (APG*H + H + APG + 512)
#define ATT_SMEM   (ATT_FLOATS*4 + 8)

__global__ void __launch_bounds__(512, 3) attn_kernel(const float* __restrict__ x,
                                                      float* __restrict__ out,
                                                      int mode) {
    extern __shared__ __align__(16) unsigned char smraw[];
    float* xs  = (float*)smraw;              // [64][256]
    float* qs  = xs + APG * H;               // [256]
    float* sc  = qs + H;                     // [64]
    float* red = sc + APG;                   // [512]
    uint32_t smem_base;
    asm("{ .reg .u64 t; cvta.to.shared.u64 t, %1; cvt.u32.u64 %0, t; }"
        : "=r"(smem_base) : "l"(smraw));
    uint32_t mbar  = smem_base + ATT_FLOATS * 4;
    uint32_t xs_sm = smem_base;

    int tid  = threadIdx.x;
    int lane = tid & 31;
    int w    = tid >> 5;

    if (tid == 0)
        asm volatile("mbarrier.init.shared.b64 [%0], 1;" :: "r"(mbar) : "memory");
    __syncthreads();

    int ph = 0;
    for (int b = blockIdx.x; b < NG; b += GRIDA) {
        // kick off the tile load immediately
        if (tid == 0) {
            asm volatile("mbarrier.arrive.expect_tx.shared.b64 _, [%0], %1;"
                         :: "r"(mbar), "r"(TILE_B) : "memory");
            asm volatile("cp.async.bulk.shared::cta.global.mbarrier::complete_tx::bytes "
                         "[%0], [%1], %2, [%3];"
                         :: "r"(xs_sm), "l"(x + (size_t)b * APG * H),
                            "r"(TILE_B), "r"(mbar) : "memory");
        }

        // fused LSTM pointwise -> q (overlaps TMA)
        if (tid < H) {
            int j = tid;
            float q;
            if (mode == 0) {
                q = g_q0[j];
            } else {
                const float* gr = g_gates + (size_t)b * FOURH;
                float gi = gr[j]       + g_bc[j];
                float gf = gr[256 + j] + g_bc[256 + j];
                float gg = gr[512 + j] + g_bc[512 + j];
                float go = gr[768 + j] + g_bc[768 + j];
                float cp = (mode == 1) ? g_c0[j] : g_c[(size_t)b * H + j];
                float c  = sigmoidf_(gf) * cp + sigmoidf_(gi) * tanhf(gg);
                q = sigmoidf_(go) * tanhf(c);
                if (mode == 1) g_c[(size_t)b * H + j] = c;
                if (mode == 2) out[(size_t)b * (2 * H) + j] = q;
            }
            qs[j] = q;
        }

        // wait for the tile
        {
            uint32_t done;
            do {
                asm volatile(
                    "{ .reg .pred p; "
                    "mbarrier.try_wait.parity.acquire.cta.shared::cta.b64 p, [%1], %2, 0x989680; "
                    "selp.b32 %0, 1, 0, p; }"
                    : "=r"(done) : "r"(mbar), "r"(ph) : "memory");
            } while (!done);
            ph ^= 1;
        }
        __syncthreads();

        // scores: 16 warps x 4 atoms
        float qreg[8];
        #pragma unroll
        for (int k = 0; k < 8; ++k) qreg[k] = qs[lane + 32 * k];
        #pragma unroll
        for (int aa = 0; aa < 4; ++aa) {
            int a = w * 4 + aa;
            const float* xr = xs + a * H;
            float p = 0.0f;
            #pragma unroll
            for (int k = 0; k < 8; ++k)
                p = fmaf(xr[lane + 32 * k], qreg[k], p);
            #pragma unroll
            for (int off = 16; off; off >>= 1)
                p += __shfl_xor_sync(0xffffffffu, p, off);
            if (lane == 0) sc[a] = p;
        }
        __syncthreads();

        // softmax over 64 (warp 0)
        if (w == 0) {
            float v0 = sc[lane], v1 = sc[lane + 32];
            float mx = fmaxf(v0, v1);
            #pragma unroll
            for (int off = 16; off; off >>= 1)
                mx = fmaxf(mx, __shfl_xor_sync(0xffffffffu, mx, off));
            float e0 = __expf(v0 - mx), e1 = __expf(v1 - mx);
            float s = e0 + e1;
            #pragma unroll
            for (int off = 16; off; off >>= 1)
                s += __shfl_xor_sync(0xffffffffu, s, off);
            float inv = 1.0f / s;
            sc[lane]      = e0 * inv;
            sc[lane + 32] = e1 * inv;
        }
        __syncthreads();

        // weighted sum: 512 threads, 2 halves of atoms
        {
            int j    = tid & (H - 1);
            int half = tid >> 8;
            const float* Xh = xs + half * 32 * H;
            float r = 0.0f;
            #pragma unroll
            for (int a0 = 0; a0 < 32; ++a0)
                r = fmaf(sc[half * 32 + a0], Xh[a0 * H + j], r);
            red[tid] = r;
        }
        __syncthreads();
        if (tid < H) {
            float rr = red[tid] + red[tid + H];
            g_h[(size_t)b * H + tid] = rr;
            if (mode == 2) out[(size_t)b * (2 * H) + H + tid] = rr;
        }
        __syncthreads();   // all reads of xs done before next load
    }
}

// ---------------- launch ----------------
extern "C" void kernel_launch(void* const* d_in, const int* in_sizes, int n_in,
                              void* d_out, int out_size) {
    const float* x    = (const float*)d_in[0];
    const float* W_ih = (const float*)d_in[3];
    const float* W_hh = (const float*)d_in[4];
    const float* b_ih = (const float*)d_in[5];
    const float* b_hh = (const float*)d_in[6];
    float* out = (float*)d_out;

    cudaFuncSetAttribute(attn_kernel,
                         cudaFuncAttributeMaxDynamicSharedMemorySize,
                         (int)ATT_SMEM);

    prep_kernel<<<1024, 256>>>(W_ih, W_hh, b_ih, b_hh);

    dim3 ggrid(FOURH / 64, NG / 128);

    attn_kernel<<<GRIDA, 512, ATT_SMEM>>>(x, nullptr, 0);   // step 0
    gemm_gates_kernel<<<ggrid, 256>>>();
    attn_kernel<<<GRIDA, 512, ATT_SMEM>>>(x, nullptr, 1);   // step 1
    gemm_gates_kernel<<<ggrid, 256>>>();
    attn_kernel<<<GRIDA, 512, ATT_SMEM>>>(x, out, 2);       // step 2
}